// round 11
// baseline (speedup 1.0000x reference)
#include <cuda_runtime.h>
#include <cuda_bf16.h>
#include <math.h>
#include <stdint.h>

#define T_DIM 1024
#define S_DIM 128
#define H_DIM 512
#define LN_EPS 1e-5f

#define KSPLIT 1536                 // 3 * 512: hi*hi + hi*lo + lo*hi
#define KCHUNK 64                   // K staged per smem tile
#define NCHUNKS (KSPLIT / KCHUNK)   // 24
#define MT 64
#define NT 64
#define LDS_STRIDE 72               // bf16 elems per smem row (64 + 8 pad)

// Scratch (allocation-free rule: __device__ globals)
__device__ float d_gt[T_DIM * H_DIM];
__device__ float d_gs[S_DIM * H_DIM];
__device__ __nv_bfloat16 d_Abf[(T_DIM + S_DIM) * KSPLIT]; // [hi, hi, lo]
__device__ __nv_bfloat16 d_Wt[H_DIM * KSPLIT];            // wt: [hi, lo, hi]
__device__ __nv_bfloat16 d_Ws[H_DIM * KSPLIT];            // ws: [hi, lo, hi]

// ---------------------------------------------------------------------------
// Conversions
// ---------------------------------------------------------------------------
__global__ __launch_bounds__(256) void convA_kernel(
    const float* __restrict__ text, const float* __restrict__ sstruct)
{
    const int r = blockIdx.x;
    const float* src = (r < T_DIM) ? (text + (size_t)r * H_DIM)
                                   : (sstruct + (size_t)(r - T_DIM) * H_DIM);
    __nv_bfloat16* dst = d_Abf + (size_t)r * KSPLIT;
    for (int j = threadIdx.x; j < KSPLIT; j += 256) {
        int sec = j >> 9;
        int k   = j & 511;
        float x = src[k];
        __nv_bfloat16 h = __float2bfloat16(x);
        dst[j] = (sec == 2) ? __float2bfloat16(x - __bfloat162float(h)) : h;
    }
}

__global__ __launch_bounds__(256) void convW_kernel(const float* __restrict__ W)
{
    const int n = blockIdx.x;
    const float* wrow = W + (size_t)n * 1024;
    __nv_bfloat16* dt = d_Wt + (size_t)n * KSPLIT;
    __nv_bfloat16* ds = d_Ws + (size_t)n * KSPLIT;
    for (int j = threadIdx.x; j < KSPLIT; j += 256) {
        int sec = j >> 9;
        int k   = j & 511;
        {
            float x = wrow[k];
            __nv_bfloat16 h = __float2bfloat16(x);
            dt[j] = (sec == 1) ? __float2bfloat16(x - __bfloat162float(h)) : h;
        }
        {
            float x = wrow[512 + k];
            __nv_bfloat16 h = __float2bfloat16(x);
            ds[j] = (sec == 1) ? __float2bfloat16(x - __bfloat162float(h)) : h;
        }
    }
}

// ---------------------------------------------------------------------------
// Warp-level HMMA GEMM: C[MT x NT] = A'[MT x 1536] @ B'[NT x 1536]^T (fp32 acc)
// mma.sync.aligned.m16n8k16.row.col.f32.bf16.bf16.f32
// 128 threads = 4 warps; warp (wm, wn) owns a 32x32 quadrant = 2 x 4 frags.
// Grid: (512/64) x (1152/64) = 8 x 18 = 144 CTAs.
// ---------------------------------------------------------------------------
__global__ __launch_bounds__(128) void mma_gemm_kernel()
{
    __shared__ __nv_bfloat16 As[MT][LDS_STRIDE];   // 9 KB
    __shared__ __nv_bfloat16 Bs[NT][LDS_STRIDE];   // 9 KB

    const int tid  = threadIdx.x;
    const int wid  = tid >> 5;
    const int lane = tid & 31;
    const int wm   = wid & 1;          // 0..1 -> m offset 0/32
    const int wn   = wid >> 1;         // 0..1 -> n offset 0/32

    const int bcol  = blockIdx.x * NT;     // 0..448 (h)
    const int browg = blockIdx.y * MT;     // 0..1088 (combined rows)

    const __nv_bfloat16* __restrict__ Bsrc = (browg < T_DIM) ? d_Wt : d_Ws;
    float* __restrict__ C = (browg < T_DIM)
        ? (d_gt + (size_t)browg * H_DIM)
        : (d_gs + (size_t)(browg - T_DIM) * H_DIM);

    // Accumulators: 2 (mi) x 4 (ni) x 4 f32
    float acc[2][4][4];
    #pragma unroll
    for (int i = 0; i < 2; i++)
        #pragma unroll
        for (int j = 0; j < 4; j++)
            #pragma unroll
            for (int q = 0; q < 4; q++) acc[i][j][q] = 0.f;

    // Staging map: 64 rows x 64 bf16; 2 threads/row, each stages a
    // contiguous 32-bf16 half-row = 4 uint4.
    const int srow  = tid >> 1;               // 0..63
    const int shalf = (tid & 1) * 32;         // bf16 offset: 0 or 32

    const __nv_bfloat16* Aptr = d_Abf + (size_t)(browg + srow) * KSPLIT + shalf;
    const __nv_bfloat16* Bptr = Bsrc  + (size_t)(bcol  + srow) * KSPLIT + shalf;

    // Fragment row/col bases (canonical m16n8k16 layout)
    const int frow = lane >> 2;              // 0..7
    const int fk   = (lane & 3) * 2;         // 0,2,4,6

    for (int c = 0; c < NCHUNKS; c++) {
        const size_t ko = (size_t)c * KCHUNK;
        // Load 4+4 uint4 per thread from global (L2-resident after 1st pass)
        uint4 va0 = *(const uint4*)(Aptr + ko);
        uint4 va1 = *(const uint4*)(Aptr + ko + 8);
        uint4 va2 = *(const uint4*)(Aptr + ko + 16);
        uint4 va3 = *(const uint4*)(Aptr + ko + 24);
        uint4 vb0 = *(const uint4*)(Bptr + ko);
        uint4 vb1 = *(const uint4*)(Bptr + ko + 8);
        uint4 vb2 = *(const uint4*)(Bptr + ko + 16);
        uint4 vb3 = *(const uint4*)(Bptr + ko + 24);
        __syncthreads();   // previous chunk's consumers done
        *(uint4*)&As[srow][shalf]      = va0;
        *(uint4*)&As[srow][shalf + 8]  = va1;
        *(uint4*)&As[srow][shalf + 16] = va2;
        *(uint4*)&As[srow][shalf + 24] = va3;
        *(uint4*)&Bs[srow][shalf]      = vb0;
        *(uint4*)&Bs[srow][shalf + 8]  = vb1;
        *(uint4*)&Bs[srow][shalf + 16] = vb2;
        *(uint4*)&Bs[srow][shalf + 24] = vb3;
        __syncthreads();

        #pragma unroll
        for (int ks = 0; ks < KCHUNK; ks += 16) {
            // A fragments for both m16 tiles
            uint32_t afr[2][4];
            #pragma unroll
            for (int mi = 0; mi < 2; mi++) {
                const int rb = wm * 32 + mi * 16;
                afr[mi][0] = *(const uint32_t*)&As[rb + frow    ][ks + fk    ];
                afr[mi][1] = *(const uint32_t*)&As[rb + frow + 8][ks + fk    ];
                afr[mi][2] = *(const uint32_t*)&As[rb + frow    ][ks + fk + 8];
                afr[mi][3] = *(const uint32_t*)&As[rb + frow + 8][ks + fk + 8];
            }
            #pragma unroll
            for (int ni = 0; ni < 4; ni++) {
                const int nb = wn * 32 + ni * 8;
                uint32_t b0 = *(const uint32_t*)&Bs[nb + frow][ks + fk    ];
                uint32_t b1 = *(const uint32_t*)&Bs[nb + frow][ks + fk + 8];
                #pragma unroll
                for (int mi = 0; mi < 2; mi++) {
                    asm volatile(
                        "mma.sync.aligned.m16n8k16.row.col.f32.bf16.bf16.f32 "
                        "{%0,%1,%2,%3}, {%4,%5,%6,%7}, {%8,%9}, {%0,%1,%2,%3};"
                        : "+f"(acc[mi][ni][0]), "+f"(acc[mi][ni][1]),
                          "+f"(acc[mi][ni][2]), "+f"(acc[mi][ni][3])
                        : "r"(afr[mi][0]), "r"(afr[mi][1]),
                          "r"(afr[mi][2]), "r"(afr[mi][3]),
                          "r"(b0), "r"(b1));
                }
            }
        }
    }

    // Epilogue: c0,c1 at (row, col..col+1); c2,c3 at (row+8, col..col+1)
    #pragma unroll
    for (int mi = 0; mi < 2; mi++) {
        const int row = wm * 32 + mi * 16 + frow;
        #pragma unroll
        for (int ni = 0; ni < 4; ni++) {
            const int col = bcol + wn * 32 + ni * 8 + fk;
            *(float2*)(C + (size_t)row * H_DIM + col) =
                make_float2(acc[mi][ni][0], acc[mi][ni][1]);
            *(float2*)(C + (size_t)(row + 8) * H_DIM + col) =
                make_float2(acc[mi][ni][2], acc[mi][ni][3]);
        }
    }
}

// ---------------------------------------------------------------------------
// fuse2 (measured ~93% of HBM): store-only hot loop.  UNCHANGED.
// ---------------------------------------------------------------------------
#define HC 32
#define TT 64

__global__ __launch_bounds__(256) void fuse2_kernel(
    const float* __restrict__ text,
    const float* __restrict__ sstruct,
    const int*   __restrict__ mask,
    const float* __restrict__ gate_b,
    float* __restrict__ xout,
    float* __restrict__ gates)
{
    __shared__ float gs_s[S_DIM][HC];
    __shared__ float st_s[S_DIM][HC];

    const int tid = threadIdx.x;
    const int hx  = tid & 7;
    const int ts  = tid >> 3;
    const int h0  = blockIdx.x * HC;
    const int t0  = blockIdx.y * TT;

    #pragma unroll
    for (int i = tid; i < S_DIM * (HC / 4); i += 256) {
        int s  = i >> 3;
        int c4 = (i & 7) * 4;
        *(float4*)&gs_s[s][c4] = *(const float4*)(d_gs    + (size_t)s * H_DIM + h0 + c4);
        *(float4*)&st_s[s][c4] = *(const float4*)(sstruct + (size_t)s * H_DIM + h0 + c4);
    }
    __syncthreads();

    const int h  = h0 + hx * 4;
    const int r0 = t0 + ts;
    const int r1 = t0 + ts + 32;

    const float4 bias = *(const float4*)(gate_b + h);

    float4 gtb0, gtb1;
    {
        float4 a = *(const float4*)(d_gt + (size_t)r0 * H_DIM + h);
        float4 b = *(const float4*)(d_gt + (size_t)r1 * H_DIM + h);
        gtb0 = make_float4(a.x + bias.x, a.y + bias.y, a.z + bias.z, a.w + bias.w);
        gtb1 = make_float4(b.x + bias.x, b.y + bias.y, b.z + bias.z, b.w + bias.w);
    }
    float4 acc0 = make_float4(0.f, 0.f, 0.f, 0.f);
    float4 acc1 = make_float4(0.f, 0.f, 0.f, 0.f);

    const int* __restrict__ m0p = mask + (size_t)r0 * S_DIM;
    const int* __restrict__ m1p = mask + (size_t)r1 * S_DIM;
    float* __restrict__ g0p = gates + (size_t)r0 * S_DIM * H_DIM + h;
    float* __restrict__ g1p = gates + (size_t)r1 * S_DIM * H_DIM + h;

    #pragma unroll 4
    for (int s = 0; s < S_DIM; s++) {
        const float4 gs4 = *(const float4*)&gs_s[s][hx * 4];
        const float4 sv4 = *(const float4*)&st_s[s][hx * 4];
        const bool m0 = (m0p[s] != 0);
        const bool m1 = (m1p[s] != 0);

        float4 g0, g1;
        g0.x = m0 ? fmaxf(gtb0.x + gs4.x, 0.f) : 0.f;
        g0.y = m0 ? fmaxf(gtb0.y + gs4.y, 0.f) : 0.f;
        g0.z = m0 ? fmaxf(gtb0.z + gs4.z, 0.f) : 0.f;
        g0.w = m0 ? fmaxf(gtb0.w + gs4.w, 0.f) : 0.f;
        g1.x = m1 ? fmaxf(gtb1.x + gs4.x, 0.f) : 0.f;
        g1.y = m1 ? fmaxf(gtb1.y + gs4.y, 0.f) : 0.f;
        g1.z = m1 ? fmaxf(gtb1.z + gs4.z, 0.f) : 0.f;
        g1.w = m1 ? fmaxf(gtb1.w + gs4.w, 0.f) : 0.f;

        __stcs((float4*)(g0p + (size_t)s * H_DIM), g0);
        __stcs((float4*)(g1p + (size_t)s * H_DIM), g1);

        acc0.x = fmaf(g0.x, sv4.x, acc0.x);
        acc0.y = fmaf(g0.y, sv4.y, acc0.y);
        acc0.z = fmaf(g0.z, sv4.z, acc0.z);
        acc0.w = fmaf(g0.w, sv4.w, acc0.w);
        acc1.x = fmaf(g1.x, sv4.x, acc1.x);
        acc1.y = fmaf(g1.y, sv4.y, acc1.y);
        acc1.z = fmaf(g1.z, sv4.z, acc1.z);
        acc1.w = fmaf(g1.w, sv4.w, acc1.w);
    }

    {
        float4 t4 = *(const float4*)(text + (size_t)r0 * H_DIM + h);
        *(float4*)(xout + (size_t)r0 * H_DIM + h) =
            make_float4(t4.x + acc0.x, t4.y + acc0.y, t4.z + acc0.z, t4.w + acc0.w);
    }
    {
        float4 t4 = *(const float4*)(text + (size_t)r1 * H_DIM + h);
        *(float4*)(xout + (size_t)r1 * H_DIM + h) =
            make_float4(t4.x + acc1.x, t4.y + acc1.y, t4.z + acc1.z, t4.w + acc1.w);
    }
}

// ---------------------------------------------------------------------------
// In-place LayerNorm. UNCHANGED.
// ---------------------------------------------------------------------------
__global__ __launch_bounds__(256) void ln_kernel(
    float* __restrict__ x,
    const float* __restrict__ gamma,
    const float* __restrict__ beta)
{
    const int tid = threadIdx.x;
    const int h4  = tid & 127;
    const int tg  = tid >> 7;
    const int h   = h4 * 4;
    const int r   = blockIdx.x * 2 + tg;

    __shared__ float red[2][2][4];

    float4 v = *(const float4*)(x + (size_t)r * H_DIM + h);
    float s1 = v.x + v.y + v.z + v.w;
    float s2 = v.x * v.x + v.y * v.y + v.z * v.z + v.w * v.w;

    const int lane = tid & 31;
    const int wg   = (tid >> 5) & 3;
    #pragma unroll
    for (int o = 16; o > 0; o >>= 1) {
        s1 += __shfl_xor_sync(0xFFFFFFFFu, s1, o);
        s2 += __shfl_xor_sync(0xFFFFFFFFu, s2, o);
    }
    if (lane == 0) { red[0][tg][wg] = s1; red[1][tg][wg] = s2; }
    __syncthreads();

    s1 = red[0][tg][0] + red[0][tg][1] + red[0][tg][2] + red[0][tg][3];
    s2 = red[1][tg][0] + red[1][tg][1] + red[1][tg][2] + red[1][tg][3];
    float mu  = s1 * (1.f / H_DIM);
    float var = s2 * (1.f / H_DIM) - mu * mu;
    float inv = rsqrtf(var + LN_EPS);

    const float4 gm = *(const float4*)(gamma + h);
    const float4 bt = *(const float4*)(beta  + h);
    float4 o;
    o.x = (v.x - mu) * inv * gm.x + bt.x;
    o.y = (v.y - mu) * inv * gm.y + bt.y;
    o.z = (v.z - mu) * inv * gm.z + bt.z;
    o.w = (v.w - mu) * inv * gm.w + bt.w;
    *(float4*)(x + (size_t)r * H_DIM + h) = o;
}

// ---------------------------------------------------------------------------
extern "C" void kernel_launch(void* const* d_in, const int* in_sizes, int n_in,
                              void* d_out, int out_size)
{
    const float* text    = (const float*)d_in[0];
    const float* sstruct = (const float*)d_in[1];
    const int*   mask    = (const int*)  d_in[2];
    const float* gate_w  = (const float*)d_in[3];
    const float* gate_b  = (const float*)d_in[4];
    const float* gamma   = (const float*)d_in[5];
    const float* beta    = (const float*)d_in[6];

    float* enriched = (float*)d_out;
    float* gates    = (float*)d_out + (size_t)T_DIM * H_DIM;

    convA_kernel<<<T_DIM + S_DIM, 256>>>(text, sstruct);
    convW_kernel<<<H_DIM, 256>>>(gate_w);
    {
        dim3 grd(H_DIM / NT, (T_DIM + S_DIM) / MT);   // 8 x 18 = 144 CTAs
        mma_gemm_kernel<<<grd, 128>>>();
    }
    {
        dim3 grd(H_DIM / HC, T_DIM / TT);             // 16 x 16
        fuse2_kernel<<<grd, 256>>>(text, sstruct, mask, gate_b,
                                   enriched, gates);
    }
    ln_kernel<<<T_DIM / 2, 256>>>(enriched, gamma, beta);
}

// round 12
// speedup vs baseline: 1.0591x; 1.0591x over previous
#include <cuda_runtime.h>
#include <cuda_bf16.h>
#include <math.h>
#include <stdint.h>

#define T_DIM 1024
#define S_DIM 128
#define H_DIM 512
#define LN_EPS 1e-5f

#define KSPLIT 1536                 // 3 * 512: hi*hi + hi*lo + lo*hi
#define KCHUNK 64                   // K staged per smem tile
#define NCHUNKS (KSPLIT / KCHUNK)   // 24
#define MT 64
#define NT 64
#define LDS_STRIDE 72               // bf16 elems per smem row (64 + 8 pad)

// Scratch (allocation-free rule: __device__ globals)
__device__ float d_gt[T_DIM * H_DIM];
__device__ float d_gs[S_DIM * H_DIM];
__device__ __nv_bfloat16 d_Abf[(T_DIM + S_DIM) * KSPLIT]; // [hi, hi, lo]
__device__ __nv_bfloat16 d_Wt[H_DIM * KSPLIT];            // wt: [hi, lo, hi]
__device__ __nv_bfloat16 d_Ws[H_DIM * KSPLIT];            // ws: [hi, lo, hi]

// ---------------------------------------------------------------------------
// cp.async helpers (baseline Ampere PTX — compiles at sm_103)
// ---------------------------------------------------------------------------
__device__ __forceinline__ void cp_async16(uint32_t dst_smem, const void* src) {
    asm volatile("cp.async.cg.shared.global [%0], [%1], 16;"
                 :: "r"(dst_smem), "l"(src));
}
#define CP_COMMIT() asm volatile("cp.async.commit_group;" ::: "memory")
#define CP_WAIT(n)  asm volatile("cp.async.wait_group %0;" :: "n"(n) : "memory")

// ---------------------------------------------------------------------------
// Merged conversion: blocks [0,1152) build A' rows; [1152,1664) build W rows.
// ---------------------------------------------------------------------------
__global__ __launch_bounds__(256) void conv_kernel(
    const float* __restrict__ text, const float* __restrict__ sstruct,
    const float* __restrict__ W)
{
    const int b = blockIdx.x;
    if (b < T_DIM + S_DIM) {
        const int r = b;
        const float* src = (r < T_DIM) ? (text + (size_t)r * H_DIM)
                                       : (sstruct + (size_t)(r - T_DIM) * H_DIM);
        __nv_bfloat16* dst = d_Abf + (size_t)r * KSPLIT;
        for (int j = threadIdx.x; j < KSPLIT; j += 256) {
            int sec = j >> 9;
            int k   = j & 511;
            float x = src[k];
            __nv_bfloat16 h = __float2bfloat16(x);
            dst[j] = (sec == 2) ? __float2bfloat16(x - __bfloat162float(h)) : h;
        }
    } else {
        const int n = b - (T_DIM + S_DIM);
        const float* wrow = W + (size_t)n * 1024;
        __nv_bfloat16* dt = d_Wt + (size_t)n * KSPLIT;
        __nv_bfloat16* ds = d_Ws + (size_t)n * KSPLIT;
        for (int j = threadIdx.x; j < KSPLIT; j += 256) {
            int sec = j >> 9;
            int k   = j & 511;
            {
                float x = wrow[k];
                __nv_bfloat16 h = __float2bfloat16(x);
                dt[j] = (sec == 1) ? __float2bfloat16(x - __bfloat162float(h)) : h;
            }
            {
                float x = wrow[512 + k];
                __nv_bfloat16 h = __float2bfloat16(x);
                ds[j] = (sec == 1) ? __float2bfloat16(x - __bfloat162float(h)) : h;
            }
        }
    }
}

// ---------------------------------------------------------------------------
// HMMA GEMM with double-buffered cp.async staging.
// C[MT x NT] = A'[MT x 1536] @ B'[NT x 1536]^T, fp32 acc.
// 128 threads = 4 warps; warp (wm, wn) owns a 32x32 quadrant.
// Grid: (512/64) x (1152/64) = 8 x 18 = 144 CTAs.
// ---------------------------------------------------------------------------
__global__ __launch_bounds__(128) void mma_gemm_kernel()
{
    __shared__ __nv_bfloat16 As[2][MT][LDS_STRIDE];   // 18 KB
    __shared__ __nv_bfloat16 Bs[2][NT][LDS_STRIDE];   // 18 KB

    const int tid  = threadIdx.x;
    const int wid  = tid >> 5;
    const int lane = tid & 31;
    const int wm   = wid & 1;
    const int wn   = wid >> 1;

    const int bcol  = blockIdx.x * NT;
    const int browg = blockIdx.y * MT;

    const __nv_bfloat16* __restrict__ Bsrc = (browg < T_DIM) ? d_Wt : d_Ws;
    float* __restrict__ C = (browg < T_DIM)
        ? (d_gt + (size_t)browg * H_DIM)
        : (d_gs + (size_t)(browg - T_DIM) * H_DIM);

    float acc[2][4][4];
    #pragma unroll
    for (int i = 0; i < 2; i++)
        #pragma unroll
        for (int j = 0; j < 4; j++)
            #pragma unroll
            for (int q = 0; q < 4; q++) acc[i][j][q] = 0.f;

    // Staging: 2 threads/row, each a contiguous 32-bf16 half-row (4 x 16B).
    const int srow  = tid >> 1;
    const int shalf = (tid & 1) * 32;

    const __nv_bfloat16* Aptr = d_Abf + (size_t)(browg + srow) * KSPLIT + shalf;
    const __nv_bfloat16* Bptr = Bsrc  + (size_t)(bcol  + srow) * KSPLIT + shalf;

    uint32_t sA[2], sB[2];
    sA[0] = (uint32_t)__cvta_generic_to_shared(&As[0][srow][shalf]);
    sA[1] = (uint32_t)__cvta_generic_to_shared(&As[1][srow][shalf]);
    sB[0] = (uint32_t)__cvta_generic_to_shared(&Bs[0][srow][shalf]);
    sB[1] = (uint32_t)__cvta_generic_to_shared(&Bs[1][srow][shalf]);

    // Preload chunk 0 into buffer 0
    {
        const __nv_bfloat16* ap = Aptr;
        const __nv_bfloat16* bp = Bptr;
        #pragma unroll
        for (int q = 0; q < 4; q++) {
            cp_async16(sA[0] + q * 16, ap + q * 8);
            cp_async16(sB[0] + q * 16, bp + q * 8);
        }
        CP_COMMIT();
    }

    const int frow = lane >> 2;
    const int fk   = (lane & 3) * 2;

    for (int c = 0; c < NCHUNKS; c++) {
        const int cur = c & 1;
        if (c + 1 < NCHUNKS) {
            const int nxt = cur ^ 1;
            const __nv_bfloat16* ap = Aptr + (size_t)(c + 1) * KCHUNK;
            const __nv_bfloat16* bp = Bptr + (size_t)(c + 1) * KCHUNK;
            #pragma unroll
            for (int q = 0; q < 4; q++) {
                cp_async16(sA[nxt] + q * 16, ap + q * 8);
                cp_async16(sB[nxt] + q * 16, bp + q * 8);
            }
            CP_COMMIT();
            CP_WAIT(1);        // chunk c has landed
        } else {
            CP_WAIT(0);
        }
        __syncthreads();

        #pragma unroll
        for (int ks = 0; ks < KCHUNK; ks += 16) {
            uint32_t afr[2][4];
            #pragma unroll
            for (int mi = 0; mi < 2; mi++) {
                const int rb = wm * 32 + mi * 16;
                afr[mi][0] = *(const uint32_t*)&As[cur][rb + frow    ][ks + fk    ];
                afr[mi][1] = *(const uint32_t*)&As[cur][rb + frow + 8][ks + fk    ];
                afr[mi][2] = *(const uint32_t*)&As[cur][rb + frow    ][ks + fk + 8];
                afr[mi][3] = *(const uint32_t*)&As[cur][rb + frow + 8][ks + fk + 8];
            }
            #pragma unroll
            for (int ni = 0; ni < 4; ni++) {
                const int nb = wn * 32 + ni * 8;
                uint32_t b0 = *(const uint32_t*)&Bs[cur][nb + frow][ks + fk    ];
                uint32_t b1 = *(const uint32_t*)&Bs[cur][nb + frow][ks + fk + 8];
                #pragma unroll
                for (int mi = 0; mi < 2; mi++) {
                    asm volatile(
                        "mma.sync.aligned.m16n8k16.row.col.f32.bf16.bf16.f32 "
                        "{%0,%1,%2,%3}, {%4,%5,%6,%7}, {%8,%9}, {%0,%1,%2,%3};"
                        : "+f"(acc[mi][ni][0]), "+f"(acc[mi][ni][1]),
                          "+f"(acc[mi][ni][2]), "+f"(acc[mi][ni][3])
                        : "r"(afr[mi][0]), "r"(afr[mi][1]),
                          "r"(afr[mi][2]), "r"(afr[mi][3]),
                          "r"(b0), "r"(b1));
                }
            }
        }
        __syncthreads();   // all reads of buf 'cur' done before it is refilled
    }

    #pragma unroll
    for (int mi = 0; mi < 2; mi++) {
        const int row = wm * 32 + mi * 16 + frow;
        #pragma unroll
        for (int ni = 0; ni < 4; ni++) {
            const int col = bcol + wn * 32 + ni * 8 + fk;
            *(float2*)(C + (size_t)row * H_DIM + col) =
                make_float2(acc[mi][ni][0], acc[mi][ni][1]);
            *(float2*)(C + (size_t)(row + 8) * H_DIM + col) =
                make_float2(acc[mi][ni][2], acc[mi][ni][3]);
        }
    }
}

// ---------------------------------------------------------------------------
// fuse2: store-only hot loop. TT=32 -> grid (16, 32) = 512 CTAs (occ ~43%).
// Each thread owns one (row, float4-of-H); 1 STG.128 per s.
// ---------------------------------------------------------------------------
#define HC 32
#define TT 32

__global__ __launch_bounds__(256) void fuse2_kernel(
    const float* __restrict__ text,
    const float* __restrict__ sstruct,
    const int*   __restrict__ mask,
    const float* __restrict__ gate_b,
    float* __restrict__ xout,
    float* __restrict__ gates)
{
    __shared__ float gs_s[S_DIM][HC];
    __shared__ float st_s[S_DIM][HC];

    const int tid = threadIdx.x;
    const int hx  = tid & 7;
    const int ts  = tid >> 3;            // 0..31
    const int h0  = blockIdx.x * HC;
    const int t0  = blockIdx.y * TT;

    #pragma unroll
    for (int i = tid; i < S_DIM * (HC / 4); i += 256) {
        int s  = i >> 3;
        int c4 = (i & 7) * 4;
        *(float4*)&gs_s[s][c4] = *(const float4*)(d_gs    + (size_t)s * H_DIM + h0 + c4);
        *(float4*)&st_s[s][c4] = *(const float4*)(sstruct + (size_t)s * H_DIM + h0 + c4);
    }
    __syncthreads();

    const int h = h0 + hx * 4;
    const int r = t0 + ts;

    const float4 bias = *(const float4*)(gate_b + h);
    float4 gtb;
    {
        float4 a = *(const float4*)(d_gt + (size_t)r * H_DIM + h);
        gtb = make_float4(a.x + bias.x, a.y + bias.y, a.z + bias.z, a.w + bias.w);
    }
    float4 acc = make_float4(0.f, 0.f, 0.f, 0.f);

    const int* __restrict__ mp = mask + (size_t)r * S_DIM;
    float* __restrict__ gp = gates + (size_t)r * S_DIM * H_DIM + h;

    #pragma unroll 4
    for (int s = 0; s < S_DIM; s++) {
        const float4 gs4 = *(const float4*)&gs_s[s][hx * 4];
        const float4 sv4 = *(const float4*)&st_s[s][hx * 4];
        const bool m = (mp[s] != 0);

        float4 g;
        g.x = m ? fmaxf(gtb.x + gs4.x, 0.f) : 0.f;
        g.y = m ? fmaxf(gtb.y + gs4.y, 0.f) : 0.f;
        g.z = m ? fmaxf(gtb.z + gs4.z, 0.f) : 0.f;
        g.w = m ? fmaxf(gtb.w + gs4.w, 0.f) : 0.f;

        __stcs((float4*)(gp + (size_t)s * H_DIM), g);

        acc.x = fmaf(g.x, sv4.x, acc.x);
        acc.y = fmaf(g.y, sv4.y, acc.y);
        acc.z = fmaf(g.z, sv4.z, acc.z);
        acc.w = fmaf(g.w, sv4.w, acc.w);
    }

    {
        float4 t4 = *(const float4*)(text + (size_t)r * H_DIM + h);
        *(float4*)(xout + (size_t)r * H_DIM + h) =
            make_float4(t4.x + acc.x, t4.y + acc.y, t4.z + acc.z, t4.w + acc.w);
    }
}

// ---------------------------------------------------------------------------
// In-place LayerNorm. UNCHANGED.
// ---------------------------------------------------------------------------
__global__ __launch_bounds__(256) void ln_kernel(
    float* __restrict__ x,
    const float* __restrict__ gamma,
    const float* __restrict__ beta)
{
    const int tid = threadIdx.x;
    const int h4  = tid & 127;
    const int tg  = tid >> 7;
    const int h   = h4 * 4;
    const int r   = blockIdx.x * 2 + tg;

    __shared__ float red[2][2][4];

    float4 v = *(const float4*)(x + (size_t)r * H_DIM + h);
    float s1 = v.x + v.y + v.z + v.w;
    float s2 = v.x * v.x + v.y * v.y + v.z * v.z + v.w * v.w;

    const int lane = tid & 31;
    const int wg   = (tid >> 5) & 3;
    #pragma unroll
    for (int o = 16; o > 0; o >>= 1) {
        s1 += __shfl_xor_sync(0xFFFFFFFFu, s1, o);
        s2 += __shfl_xor_sync(0xFFFFFFFFu, s2, o);
    }
    if (lane == 0) { red[0][tg][wg] = s1; red[1][tg][wg] = s2; }
    __syncthreads();

    s1 = red[0][tg][0] + red[0][tg][1] + red[0][tg][2] + red[0][tg][3];
    s2 = red[1][tg][0] + red[1][tg][1] + red[1][tg][2] + red[1][tg][3];
    float mu  = s1 * (1.f / H_DIM);
    float var = s2 * (1.f / H_DIM) - mu * mu;
    float inv = rsqrtf(var + LN_EPS);

    const float4 gm = *(const float4*)(gamma + h);
    const float4 bt = *(const float4*)(beta  + h);
    float4 o;
    o.x = (v.x - mu) * inv * gm.x + bt.x;
    o.y = (v.y - mu) * inv * gm.y + bt.y;
    o.z = (v.z - mu) * inv * gm.z + bt.z;
    o.w = (v.w - mu) * inv * gm.w + bt.w;
    *(float4*)(x + (size_t)r * H_DIM + h) = o;
}

// ---------------------------------------------------------------------------
extern "C" void kernel_launch(void* const* d_in, const int* in_sizes, int n_in,
                              void* d_out, int out_size)
{
    const float* text    = (const float*)d_in[0];
    const float* sstruct = (const float*)d_in[1];
    const int*   mask    = (const int*)  d_in[2];
    const float* gate_w  = (const float*)d_in[3];
    const float* gate_b  = (const float*)d_in[4];
    const float* gamma   = (const float*)d_in[5];
    const float* beta    = (const float*)d_in[6];

    float* enriched = (float*)d_out;
    float* gates    = (float*)d_out + (size_t)T_DIM * H_DIM;

    conv_kernel<<<T_DIM + S_DIM + H_DIM, 256>>>(text, sstruct, gate_w);
    {
        dim3 grd(H_DIM / NT, (T_DIM + S_DIM) / MT);   // 8 x 18 = 144 CTAs
        mma_gemm_kernel<<<grd, 128>>>();
    }
    {
        dim3 grd(H_DIM / HC, T_DIM / TT);             // 16 x 32 = 512 CTAs
        fuse2_kernel<<<grd, 256>>>(text, sstruct, mask, gate_b,
                                   enriched, gates);
    }
    ln_kernel<<<T_DIM / 2, 256>>>(enriched, gamma, beta);
}